// round 12
// baseline (speedup 1.0000x reference)
#include <cuda_runtime.h>
#include <cuda_bf16.h>
#include <cstdint>

// bf16 mma.sync fused MoE-PINN — barrier-free mainloop, warp-private B staging.

__device__ __nv_bfloat16 g_We1b[6 * 512 * 1024];
__device__ __nv_bfloat16 g_We2b[6 * 1024 * 512];
__device__ float g_routing[32768 * 6];

__device__ __forceinline__ float fast_tanh(float x) {
    float e = __expf(2.0f * x);
    return 1.0f - __fdividef(2.0f, e + 1.0f);
}
__device__ __forceinline__ uint32_t smem_u32(const void* p) {
    return (uint32_t)__cvta_generic_to_shared(p);
}
__device__ __forceinline__ void ldsm_x4(uint32_t (&r)[4], uint32_t a) {
    asm volatile("ldmatrix.sync.aligned.m8n8.x4.shared.b16 {%0,%1,%2,%3}, [%4];"
        : "=r"(r[0]), "=r"(r[1]), "=r"(r[2]), "=r"(r[3]) : "r"(a));
}
__device__ __forceinline__ void ldsm_x4_t(uint32_t (&r)[4], uint32_t a) {
    asm volatile("ldmatrix.sync.aligned.m8n8.x4.trans.shared.b16 {%0,%1,%2,%3}, [%4];"
        : "=r"(r[0]), "=r"(r[1]), "=r"(r[2]), "=r"(r[3]) : "r"(a));
}
__device__ __forceinline__ void mma_bf16(float (&d)[4], const uint32_t (&a)[4],
                                         uint32_t b0, uint32_t b1) {
    asm volatile(
        "mma.sync.aligned.m16n8k16.row.col.f32.bf16.bf16.f32 "
        "{%0,%1,%2,%3}, {%4,%5,%6,%7}, {%8,%9}, {%0,%1,%2,%3};"
        : "+f"(d[0]), "+f"(d[1]), "+f"(d[2]), "+f"(d[3])
        : "r"(a[0]), "r"(a[1]), "r"(a[2]), "r"(a[3]), "r"(b0), "r"(b1));
}
__device__ __forceinline__ void cp16(uint32_t dst, const void* src) {
    asm volatile("cp.async.cg.shared.global [%0], [%1], 16;" :: "r"(dst), "l"(src));
}
__device__ __forceinline__ void cp_commit() { asm volatile("cp.async.commit_group;"); }
__device__ __forceinline__ void cp_wait0() { asm volatile("cp.async.wait_group 0;"); }
__device__ __forceinline__ void cp_wait1() { asm volatile("cp.async.wait_group 1;"); }

// ---------------- prep: convert We1/We2 to bf16 ----------------
__global__ __launch_bounds__(256) void prep_kernel(
    const float* __restrict__ We1, const float* __restrict__ We2)
{
    const size_t N4 = (size_t)6 * 512 * 1024 / 4;
    size_t i = (size_t)blockIdx.x * 256 + threadIdx.x;
    if (i < N4) {
        float4 v = ((const float4*)We1)[i];
        ((__nv_bfloat162*)g_We1b)[i * 2]     = __floats2bfloat162_rn(v.x, v.y);
        ((__nv_bfloat162*)g_We1b)[i * 2 + 1] = __floats2bfloat162_rn(v.z, v.w);
        float4 w = ((const float4*)We2)[i];
        ((__nv_bfloat162*)g_We2b)[i * 2]     = __floats2bfloat162_rn(w.x, w.y);
        ((__nv_bfloat162*)g_We2b)[i * 2 + 1] = __floats2bfloat162_rn(w.z, w.w);
    }
}

// ---------------- routing kernel (fp32, proven) ----------------
__global__ __launch_bounds__(256, 1) void routing_kernel(
    const float* __restrict__ x,
    const float* __restrict__ Wr1, const float* __restrict__ br1,
    const float* __restrict__ Wr2, const float* __restrict__ br2)
{
    extern __shared__ char smraw[];
    float* xs = (float*)smraw;
    float* w1 = xs + 64 * 512;
    float* r1 = w1 + 512 * 32;
    float* w2 = r1 + 64 * 32;
    float* b1 = w2 + 192;
    float* b2 = b1 + 32;
    const int s = blockIdx.y, b0 = blockIdx.x * 64, tid = threadIdx.x;

    for (int i = tid; i < 64 * 512 / 4; i += 256) {
        int row = i >> 7, c4 = i & 127;
        ((float4*)xs)[i] = *(const float4*)(x + (size_t)(b0 + row) * 4096 + s * 512 + c4 * 4);
    }
    const float* w1g = Wr1 + (size_t)s * 512 * 32;
    for (int i = tid; i < 512 * 32 / 4; i += 256)
        ((float4*)w1)[i] = ((const float4*)w1g)[i];
    if (tid < 32)  b1[tid] = br1[s * 32 + tid];
    if (tid < 192) w2[tid] = Wr2[s * 192 + tid];
    if (tid < 6)   b2[tid] = br2[s * 6 + tid];
    __syncthreads();
    {
        int h = tid & 31, rg = tid >> 5;
        float acc[8];
#pragma unroll
        for (int r = 0; r < 8; ++r) acc[r] = 0.f;
        for (int k = 0; k < 512; ++k) {
            float w = w1[k * 32 + h];
#pragma unroll
            for (int r = 0; r < 8; ++r)
                acc[r] = fmaf(xs[(rg * 8 + r) * 512 + k], w, acc[r]);
        }
#pragma unroll
        for (int r = 0; r < 8; ++r)
            r1[(rg * 8 + r) * 32 + h] = fmaxf(acc[r] + b1[h], 0.f);
    }
    __syncthreads();
    if (tid < 64) {
        float lg[6];
#pragma unroll
        for (int e = 0; e < 6; ++e) lg[e] = b2[e];
        for (int h = 0; h < 32; ++h) {
            float rv = r1[tid * 32 + h];
#pragma unroll
            for (int e = 0; e < 6; ++e) lg[e] = fmaf(rv, w2[h * 6 + e], lg[e]);
        }
        float mx = lg[0];
#pragma unroll
        for (int e = 1; e < 6; ++e) mx = fmaxf(mx, lg[e]);
        float sum = 0.f;
#pragma unroll
        for (int e = 0; e < 6; ++e) { lg[e] = __expf(lg[e] - mx); sum += lg[e]; }
        float inv = 1.f / sum;
        int r = (b0 + tid) * 8 + s;
#pragma unroll
        for (int e = 0; e < 6; ++e) g_routing[r * 6 + e] = lg[e] * inv;
    }
}

// ---------------- barrier-free GEMM chunk ----------------
// Warp tile 32x32 of the 64x128 chunk: wr=warp&1 rows, wc=warp>>1 cols.
// Each warp stages its own 16x32 B panel (3-buf ring, rows stride 80B).
#define LDA_X 520
#define LDA_H1 1032

template <int MODE>
__device__ __forceinline__ void mma_chunk(
    const __nv_bfloat16* __restrict__ Asm, int lda, int K,
    const __nv_bfloat16* __restrict__ Wg, int ldw,   // chunk base (col nc)
    uint32_t wsW,                                    // warp-private staging base
    const float* __restrict__ biasg,                 // bias + nc
    __nv_bfloat16* __restrict__ h1out, int nc,
    const float* __restrict__ we3g, float (*s)[3])
{
    const int tid = threadIdx.x;
    const int lane = tid & 31, warp = tid >> 5;
    const int wr = warp & 1, wc = warp >> 1;
    const int rowbase = wr * 32, colbase = wc * 32;
    const int li = lane & 15, lj = lane >> 4;

    float c[2][4][4];
#pragma unroll
    for (int mt = 0; mt < 2; ++mt)
#pragma unroll
        for (int nt = 0; nt < 4; ++nt)
#pragma unroll
            for (int v = 0; v < 4; ++v) c[mt][nt][v] = 0.f;

    const __nv_bfloat16* srcW = Wg + colbase + (size_t)(lane >> 1) * ldw + (lane & 1) * 16;
    const uint32_t dstW = wsW + (uint32_t)((lane >> 1) * 80 + (lane & 1) * 32);
    const int nst = K >> 4;

    // prologue: stages 0,1
    cp16(dstW, srcW); cp16(dstW + 16, srcW + 8); cp_commit();
    {
        const __nv_bfloat16* s1 = srcW + (size_t)16 * ldw;
        cp16(dstW + 1280, s1); cp16(dstW + 1296, s1 + 8); cp_commit();
    }

    const __nv_bfloat16* a0p = Asm + (size_t)(rowbase + li) * lda + lj * 8;
    const __nv_bfloat16* a1p = a0p + (size_t)16 * lda;
    const uint32_t bq = wsW + (uint32_t)(li * 80 + lj * 16);

    int bcur = 0, bfill = 2;
    for (int st = 0; st < nst; ++st) {
        if (st + 1 < nst) cp_wait1(); else cp_wait0();
        uint32_t A[2][4], B[2][4];
        ldsm_x4(A[0], smem_u32(a0p + st * 16));
        ldsm_x4(A[1], smem_u32(a1p + st * 16));
        const uint32_t wb = bq + (uint32_t)bcur * 1280;
        ldsm_x4_t(B[0], wb);
        ldsm_x4_t(B[1], wb + 32);
        if (++bcur == 3) bcur = 0;
        if (st + 2 < nst) {
            const __nv_bfloat16* sg = srcW + (size_t)(st + 2) * 16 * ldw;
            const uint32_t dd = dstW + (uint32_t)bfill * 1280;
            cp16(dd, sg); cp16(dd + 16, sg + 8); cp_commit();
            if (++bfill == 3) bfill = 0;
        }
#pragma unroll
        for (int mt = 0; mt < 2; ++mt)
#pragma unroll
            for (int nt = 0; nt < 4; ++nt)
                mma_bf16(c[mt][nt], A[mt], B[nt >> 1][(nt & 1) * 2],
                         B[nt >> 1][(nt & 1) * 2 + 1]);
    }

    // epilogue
#pragma unroll
    for (int mt = 0; mt < 2; ++mt) {
#pragma unroll
        for (int nt = 0; nt < 4; ++nt) {
            const int colc = colbase + nt * 8 + 2 * (lane & 3);
            float2 bb = *(const float2*)(biasg + colc);
            float t0 = fast_tanh(c[mt][nt][0] + bb.x);
            float t1 = fast_tanh(c[mt][nt][1] + bb.y);
            float t2 = fast_tanh(c[mt][nt][2] + bb.x);
            float t3 = fast_tanh(c[mt][nt][3] + bb.y);
            const int ra = rowbase + mt * 16 + (lane >> 2);
            if (MODE == 0) {
                __nv_bfloat162 p0 = __floats2bfloat162_rn(t0, t1);
                __nv_bfloat162 p1 = __floats2bfloat162_rn(t2, t3);
                *(__nv_bfloat162*)&h1out[(size_t)ra * LDA_H1 + nc + colc] = p0;
                *(__nv_bfloat162*)&h1out[(size_t)(ra + 8) * LDA_H1 + nc + colc] = p1;
            } else {
                const float* w3a = we3g + (size_t)(nc + colc) * 3;
#pragma unroll
                for (int o = 0; o < 3; ++o) {
                    float wa = w3a[o], wb2 = w3a[3 + o];
                    s[mt * 2 + 0][o] += t0 * wa + t1 * wb2;
                    s[mt * 2 + 1][o] += t2 * wa + t3 * wb2;
                }
            }
        }
    }
}

// ---------------- main fused kernel: 512 CTAs x 256 threads ----------------
// smem: xs 66560 | h1 132096 | ws 30720 | rout 1536 | oacc 1024 => 231936
__global__ __launch_bounds__(256, 1) void moe_kernel(
    const float* __restrict__ x,
    const float* __restrict__ be1, const float* __restrict__ be2,
    const float* __restrict__ We3, const float* __restrict__ be3,
    const float* __restrict__ Wa1, const float* __restrict__ ba1,
    const float* __restrict__ Wa2, const float* __restrict__ ba2,
    float* __restrict__ out)
{
    extern __shared__ char smraw[];
    __nv_bfloat16* xs   = (__nv_bfloat16*)(smraw);
    __nv_bfloat16* h1s  = (__nv_bfloat16*)(smraw + 66560);
    char*          wsb  = smraw + 198656;
    float*         rout = (float*)(smraw + 229376);
    float*         oacc = (float*)(smraw + 230912);

    const int tid = threadIdx.x;
    const int lane = tid & 31, warp = tid >> 5;
    const int wr = warp & 1, wc = warp >> 1;
    const int r0 = blockIdx.x * 64;
    const uint32_t wsW = smem_u32(wsb) + (uint32_t)warp * 3840;

    for (int i = tid; i < 64 * 512 / 4; i += 256) {
        int row = i >> 7, c4 = i & 127;
        float4 v = *(const float4*)(x + (size_t)(r0 + row) * 512 + c4 * 4);
        __nv_bfloat162* d = (__nv_bfloat162*)&xs[(size_t)row * LDA_X + c4 * 4];
        d[0] = __floats2bfloat162_rn(v.x, v.y);
        d[1] = __floats2bfloat162_rn(v.z, v.w);
    }
    for (int i = tid; i < 384; i += 256) rout[i] = g_routing[(size_t)r0 * 6 + i];
    if (tid < 128) { oacc[tid] = 0.f; oacc[tid + 128] = 0.f; }
    __syncthreads();

    for (int e = 0; e < 6; ++e) {
        // L1: h1 = tanh(x @ We1 + be1)  (no intra-phase barriers)
        const __nv_bfloat16* W1 = g_We1b + (size_t)e * 512 * 1024;
        const float* b1 = be1 + e * 1024;
        for (int nc = 0; nc < 1024; nc += 128)
            mma_chunk<0>(xs, LDA_X, 512, W1 + nc, 1024, wsW, b1 + nc,
                         h1s, nc, nullptr, nullptr);
        __syncthreads();   // h1 complete before any warp reads it

        // L2+L3 fused
        float s[4][3];
#pragma unroll
        for (int rt = 0; rt < 4; ++rt)
#pragma unroll
            for (int o = 0; o < 3; ++o) s[rt][o] = 0.f;

        const __nv_bfloat16* W2 = g_We2b + (size_t)e * 1024 * 512;
        const float* b2 = be2 + e * 512;
        const float* w3 = We3 + (size_t)e * 1536;
        for (int nc = 0; nc < 512; nc += 128)
            mma_chunk<1>(h1s, LDA_H1, 1024, W2 + nc, 512, wsW, b2 + nc,
                         nullptr, nc, w3, s);

#pragma unroll
        for (int rt = 0; rt < 4; ++rt)
#pragma unroll
            for (int o = 0; o < 3; ++o) {
                s[rt][o] += __shfl_xor_sync(0xffffffffu, s[rt][o], 1);
                s[rt][o] += __shfl_xor_sync(0xffffffffu, s[rt][o], 2);
            }
        if ((lane & 3) == 0) {
            float bz[3];
#pragma unroll
            for (int o = 0; o < 3; ++o)
                bz[o] = (wc == 0) ? be3[e * 3 + o] : 0.f;
#pragma unroll
            for (int rt = 0; rt < 4; ++rt) {
                int row = wr * 32 + (rt >> 1) * 16 + (lane >> 2) + 8 * (rt & 1);
                float rw = rout[row * 6 + e];
#pragma unroll
                for (int o = 0; o < 3; ++o)
                    atomicAdd(&oacc[row * 4 + o], rw * (s[rt][o] + bz[o]));
            }
        }
        __syncthreads();   // oacc/h1 settle before next expert overwrites h1
    }

    if (tid < 8) {
        float f0 = 0.f, f1 = 0.f, f2 = 0.f;
#pragma unroll
        for (int i = 0; i < 8; ++i) {
            f0 += oacc[(tid * 8 + i) * 4 + 0];
            f1 += oacc[(tid * 8 + i) * 4 + 1];
            f2 += oacc[(tid * 8 + i) * 4 + 2];
        }
        f0 *= 0.125f; f1 *= 0.125f; f2 *= 0.125f;
        float a1[16];
#pragma unroll
        for (int j = 0; j < 16; ++j) {
            float v = ba1[j] + f0 * Wa1[j] + f1 * Wa1[16 + j] + f2 * Wa1[32 + j];
            a1[j] = fmaxf(v, 0.f);
        }
        int b = blockIdx.x * 8 + tid;
#pragma unroll
        for (int o = 0; o < 3; ++o) {
            float v = ba2[o];
#pragma unroll
            for (int j = 0; j < 16; ++j) v = fmaf(a1[j], Wa2[j * 3 + o], v);
            out[b * 3 + o] = v;
        }
    }
}

// ---------------- launch ----------------
extern "C" void kernel_launch(void* const* d_in, const int* in_sizes, int n_in,
                              void* d_out, int out_size) {
    const float* x   = (const float*)d_in[0];
    const float* Wr1 = (const float*)d_in[1];
    const float* br1 = (const float*)d_in[2];
    const float* Wr2 = (const float*)d_in[3];
    const float* br2 = (const float*)d_in[4];
    const float* We1 = (const float*)d_in[5];
    const float* be1 = (const float*)d_in[6];
    const float* We2 = (const float*)d_in[7];
    const float* be2 = (const float*)d_in[8];
    const float* We3 = (const float*)d_in[9];
    const float* be3 = (const float*)d_in[10];
    const float* Wa1 = (const float*)d_in[11];
    const float* ba1 = (const float*)d_in[12];
    const float* Wa2 = (const float*)d_in[13];
    const float* ba2 = (const float*)d_in[14];
    float* out = (float*)d_out;

    const int SMEM_R = (64 * 512 + 512 * 32 + 64 * 32 + 192 + 32 + 8) * 4;
    const int SMEM_M = 231936;

    cudaFuncSetAttribute(routing_kernel, cudaFuncAttributeMaxDynamicSharedMemorySize, SMEM_R);
    cudaFuncSetAttribute(moe_kernel, cudaFuncAttributeMaxDynamicSharedMemorySize, SMEM_M);

    prep_kernel<<<3072, 256>>>(We1, We2);
    routing_kernel<<<dim3(64, 8), 256, SMEM_R>>>(x, Wr1, br1, Wr2, br2);
    moe_kernel<<<512, 256, SMEM_M>>>(x, be1, be2, We3, be3,
                                     Wa1, ba1, Wa2, ba2, out);
}

// round 13
// speedup vs baseline: 1.1394x; 1.1394x over previous
#include <cuda_runtime.h>
#include <cuda_bf16.h>
#include <cstdint>

// bf16 mma.sync fused MoE-PINN — R6 base + 32-k pair sync (6-slot ring) + rout fix.

__device__ __nv_bfloat16 g_We1b[6 * 512 * 1024];
__device__ __nv_bfloat16 g_We2b[6 * 1024 * 512];
__device__ float g_routing[32768 * 6];

__device__ __forceinline__ float fast_tanh(float x) {
    float e = __expf(2.0f * x);
    return 1.0f - __fdividef(2.0f, e + 1.0f);
}
__device__ __forceinline__ uint32_t smem_u32(const void* p) {
    return (uint32_t)__cvta_generic_to_shared(p);
}
__device__ __forceinline__ void ldsm_x4(uint32_t (&r)[4], uint32_t a) {
    asm volatile("ldmatrix.sync.aligned.m8n8.x4.shared.b16 {%0,%1,%2,%3}, [%4];"
        : "=r"(r[0]), "=r"(r[1]), "=r"(r[2]), "=r"(r[3]) : "r"(a));
}
__device__ __forceinline__ void ldsm_x4_t(uint32_t (&r)[4], uint32_t a) {
    asm volatile("ldmatrix.sync.aligned.m8n8.x4.trans.shared.b16 {%0,%1,%2,%3}, [%4];"
        : "=r"(r[0]), "=r"(r[1]), "=r"(r[2]), "=r"(r[3]) : "r"(a));
}
__device__ __forceinline__ void mma_bf16(float (&d)[4], const uint32_t (&a)[4],
                                         uint32_t b0, uint32_t b1) {
    asm volatile(
        "mma.sync.aligned.m16n8k16.row.col.f32.bf16.bf16.f32 "
        "{%0,%1,%2,%3}, {%4,%5,%6,%7}, {%8,%9}, {%0,%1,%2,%3};"
        : "+f"(d[0]), "+f"(d[1]), "+f"(d[2]), "+f"(d[3])
        : "r"(a[0]), "r"(a[1]), "r"(a[2]), "r"(a[3]), "r"(b0), "r"(b1));
}
__device__ __forceinline__ void cp16(uint32_t dst, const void* src) {
    asm volatile("cp.async.cg.shared.global [%0], [%1], 16;" :: "r"(dst), "l"(src));
}
__device__ __forceinline__ void cp_commit() { asm volatile("cp.async.commit_group;"); }
__device__ __forceinline__ void cp_wait0() { asm volatile("cp.async.wait_group 0;"); }
__device__ __forceinline__ void cp_wait1() { asm volatile("cp.async.wait_group 1;"); }
__device__ __forceinline__ void cp_wait2() { asm volatile("cp.async.wait_group 2;"); }

// ---------------- prep: convert We1/We2 to bf16 ----------------
__global__ __launch_bounds__(256) void prep_kernel(
    const float* __restrict__ We1, const float* __restrict__ We2)
{
    const size_t N4 = (size_t)6 * 512 * 1024 / 4;
    size_t i = (size_t)blockIdx.x * 256 + threadIdx.x;
    if (i < N4) {
        float4 v = ((const float4*)We1)[i];
        ((__nv_bfloat162*)g_We1b)[i * 2]     = __floats2bfloat162_rn(v.x, v.y);
        ((__nv_bfloat162*)g_We1b)[i * 2 + 1] = __floats2bfloat162_rn(v.z, v.w);
        float4 w = ((const float4*)We2)[i];
        ((__nv_bfloat162*)g_We2b)[i * 2]     = __floats2bfloat162_rn(w.x, w.y);
        ((__nv_bfloat162*)g_We2b)[i * 2 + 1] = __floats2bfloat162_rn(w.z, w.w);
    }
}

// ---------------- routing kernel (fp32, proven) ----------------
__global__ __launch_bounds__(256, 1) void routing_kernel(
    const float* __restrict__ x,
    const float* __restrict__ Wr1, const float* __restrict__ br1,
    const float* __restrict__ Wr2, const float* __restrict__ br2)
{
    extern __shared__ char smraw[];
    float* xs = (float*)smraw;
    float* w1 = xs + 64 * 512;
    float* r1 = w1 + 512 * 32;
    float* w2 = r1 + 64 * 32;
    float* b1 = w2 + 192;
    float* b2 = b1 + 32;
    const int s = blockIdx.y, b0 = blockIdx.x * 64, tid = threadIdx.x;

    for (int i = tid; i < 64 * 512 / 4; i += 256) {
        int row = i >> 7, c4 = i & 127;
        ((float4*)xs)[i] = *(const float4*)(x + (size_t)(b0 + row) * 4096 + s * 512 + c4 * 4);
    }
    const float* w1g = Wr1 + (size_t)s * 512 * 32;
    for (int i = tid; i < 512 * 32 / 4; i += 256)
        ((float4*)w1)[i] = ((const float4*)w1g)[i];
    if (tid < 32)  b1[tid] = br1[s * 32 + tid];
    if (tid < 192) w2[tid] = Wr2[s * 192 + tid];
    if (tid < 6)   b2[tid] = br2[s * 6 + tid];
    __syncthreads();
    {
        int h = tid & 31, rg = tid >> 5;
        float acc[8];
#pragma unroll
        for (int r = 0; r < 8; ++r) acc[r] = 0.f;
        for (int k = 0; k < 512; ++k) {
            float w = w1[k * 32 + h];
#pragma unroll
            for (int r = 0; r < 8; ++r)
                acc[r] = fmaf(xs[(rg * 8 + r) * 512 + k], w, acc[r]);
        }
#pragma unroll
        for (int r = 0; r < 8; ++r)
            r1[(rg * 8 + r) * 32 + h] = fmaxf(acc[r] + b1[h], 0.f);
    }
    __syncthreads();
    if (tid < 64) {
        float lg[6];
#pragma unroll
        for (int e = 0; e < 6; ++e) lg[e] = b2[e];
        for (int h = 0; h < 32; ++h) {
            float rv = r1[tid * 32 + h];
#pragma unroll
            for (int e = 0; e < 6; ++e) lg[e] = fmaf(rv, w2[h * 6 + e], lg[e]);
        }
        float mx = lg[0];
#pragma unroll
        for (int e = 1; e < 6; ++e) mx = fmaxf(mx, lg[e]);
        float sum = 0.f;
#pragma unroll
        for (int e = 0; e < 6; ++e) { lg[e] = __expf(lg[e] - mx); sum += lg[e]; }
        float inv = 1.f / sum;
        int r = (b0 + tid) * 8 + s;
#pragma unroll
        for (int e = 0; e < 6; ++e) g_routing[r * 6 + e] = lg[e] * inv;
    }
}

// ---------------- GEMM chunk: pair-synced, 6-slot staging ring --------------
#define LDA_X 520
#define LDA_H1 1032
#define WS_STRIDE 136
#define WS_BUF_E (16 * WS_STRIDE)   // 2176 elems / stage
#define WS_BUF_B (WS_BUF_E * 2)     // 4352 bytes / stage

template <int MODE>
__device__ __forceinline__ void mma_chunk(
    const __nv_bfloat16* __restrict__ Asm, int lda, int K,
    const __nv_bfloat16* __restrict__ Wg, int ldw,
    const __nv_bfloat16* __restrict__ ws, uint32_t ws_u32,
    const float* __restrict__ biasg,
    __nv_bfloat16* __restrict__ h1out, int nc,
    const float* __restrict__ we3g, float (*s)[3])
{
    const int tid = threadIdx.x;
    const int lane = tid & 31, warp = tid >> 5;
    const int wr = warp >> 2, wc = warp & 3;
    const int rowbase = wr * 32, colbase = wc * 32;
    const int li = lane & 15, lj = lane >> 4;

    float c[2][4][4];
#pragma unroll
    for (int mt = 0; mt < 2; ++mt)
#pragma unroll
        for (int nt = 0; nt < 4; ++nt)
#pragma unroll
            for (int v = 0; v < 4; ++v) c[mt][nt][v] = 0.f;

    const int crow = tid >> 4;            // 0..15
    const int ccol = (tid & 15) * 8;
    const uint32_t dst0 = ws_u32 + (uint32_t)(crow * WS_STRIDE + ccol) * 2;
    const __nv_bfloat16* src0 = Wg + (size_t)crow * ldw + ccol;
    const int nst = K >> 4;               // 32 or 64 (even)

    // prologue: stages 0..3 into slots 0..3 (previous chunk's final barrier
    // already retired all readers of these slots)
#pragma unroll
    for (int q = 0; q < 4; ++q) {
        cp16(dst0 + (uint32_t)q * WS_BUF_B, src0 + (size_t)q * 16 * ldw);
        cp_commit();
    }
    cp_wait2();
    __syncthreads();   // stages 0,1 visible

    const __nv_bfloat16* a0p = Asm + (size_t)(rowbase + li) * lda + lj * 8;
    const __nv_bfloat16* a1p = a0p + (size_t)16 * lda;
    const __nv_bfloat16* bp  = ws + li * WS_STRIDE + colbase + lj * 8;

    const int niter = nst >> 1;
    for (int it = 0; it < niter; ++it) {
        const int s0 = 2 * it, s1 = s0 + 1;

        // refill stages s0+4, s0+5 (slots ≡ stages read in iter it-1; safe
        // behind the previous iteration's barrier)
        int refills = 0;
        if (s0 + 4 < nst) {
            cp16(dst0 + (uint32_t)((s0 + 4) % 6) * WS_BUF_B,
                 src0 + (size_t)(s0 + 4) * 16 * ldw);
            cp_commit(); ++refills;
        }
        if (s0 + 5 < nst) {
            cp16(dst0 + (uint32_t)((s0 + 5) % 6) * WS_BUF_B,
                 src0 + (size_t)(s0 + 5) * 16 * ldw);
            cp_commit(); ++refills;
        }

        // compute stage s0
        {
            uint32_t a[2][4], b[2][4];
            ldsm_x4(a[0], smem_u32(a0p + s0 * 16));
            ldsm_x4(a[1], smem_u32(a1p + s0 * 16));
            const __nv_bfloat16* wb = bp + (s0 % 6) * WS_BUF_E;
            ldsm_x4_t(b[0], smem_u32(wb));
            ldsm_x4_t(b[1], smem_u32(wb + 16));
#pragma unroll
            for (int mt = 0; mt < 2; ++mt)
#pragma unroll
                for (int nt = 0; nt < 4; ++nt)
                    mma_bf16(c[mt][nt], a[mt], b[nt >> 1][(nt & 1) * 2],
                             b[nt >> 1][(nt & 1) * 2 + 1]);
        }
        // compute stage s1
        {
            uint32_t a[2][4], b[2][4];
            ldsm_x4(a[0], smem_u32(a0p + s1 * 16));
            ldsm_x4(a[1], smem_u32(a1p + s1 * 16));
            const __nv_bfloat16* wb = bp + (s1 % 6) * WS_BUF_E;
            ldsm_x4_t(b[0], smem_u32(wb));
            ldsm_x4_t(b[1], smem_u32(wb + 16));
#pragma unroll
            for (int mt = 0; mt < 2; ++mt)
#pragma unroll
                for (int nt = 0; nt < 4; ++nt)
                    mma_bf16(c[mt][nt], a[mt], b[nt >> 1][(nt & 1) * 2],
                             b[nt >> 1][(nt & 1) * 2 + 1]);
        }

        // retire so next pair (s0+2, s0+3) is landed, then publish
        if (refills == 2)      cp_wait2();
        else if (refills == 1) cp_wait1();
        else                   cp_wait0();
        __syncthreads();
    }

    // epilogue
#pragma unroll
    for (int mt = 0; mt < 2; ++mt) {
#pragma unroll
        for (int nt = 0; nt < 4; ++nt) {
            const int colc = colbase + nt * 8 + 2 * (lane & 3);
            float2 bb = *(const float2*)(biasg + colc);
            float t0 = fast_tanh(c[mt][nt][0] + bb.x);
            float t1 = fast_tanh(c[mt][nt][1] + bb.y);
            float t2 = fast_tanh(c[mt][nt][2] + bb.x);
            float t3 = fast_tanh(c[mt][nt][3] + bb.y);
            const int ra = rowbase + mt * 16 + (lane >> 2);
            if (MODE == 0) {
                __nv_bfloat162 p0 = __floats2bfloat162_rn(t0, t1);
                __nv_bfloat162 p1 = __floats2bfloat162_rn(t2, t3);
                *(__nv_bfloat162*)&h1out[(size_t)ra * LDA_H1 + nc + colc] = p0;
                *(__nv_bfloat162*)&h1out[(size_t)(ra + 8) * LDA_H1 + nc + colc] = p1;
            } else {
                const float* w3a = we3g + (size_t)(nc + colc) * 3;
#pragma unroll
                for (int o = 0; o < 3; ++o) {
                    float wa = w3a[o], wb2 = w3a[3 + o];
                    s[mt * 2 + 0][o] += t0 * wa + t1 * wb2;
                    s[mt * 2 + 1][o] += t2 * wa + t3 * wb2;
                }
            }
        }
    }
}

// ---------------- main fused kernel: 512 CTAs x 256 threads ----------------
// smem: xs 66560 | h1 132096 | ws 26112 | rout 1536 | oacc 1024 => 227328
__global__ __launch_bounds__(256, 1) void moe_kernel(
    const float* __restrict__ x,
    const float* __restrict__ be1, const float* __restrict__ be2,
    const float* __restrict__ We3, const float* __restrict__ be3,
    const float* __restrict__ Wa1, const float* __restrict__ ba1,
    const float* __restrict__ Wa2, const float* __restrict__ ba2,
    float* __restrict__ out)
{
    extern __shared__ char smraw[];
    __nv_bfloat16* xs   = (__nv_bfloat16*)(smraw);
    __nv_bfloat16* h1s  = (__nv_bfloat16*)(smraw + 66560);
    __nv_bfloat16* ws   = (__nv_bfloat16*)(smraw + 198656);
    float*         rout = (float*)(smraw + 224768);
    float*         oacc = (float*)(smraw + 226304);

    const int tid = threadIdx.x;
    const int lane = tid & 31, warp = tid >> 5;
    const int wr = warp >> 2, wc = warp & 3;
    const int r0 = blockIdx.x * 64;
    const uint32_t ws_u32 = smem_u32(ws);

    for (int i = tid; i < 64 * 512 / 4; i += 256) {
        int row = i >> 7, c4 = i & 127;
        float4 v = *(const float4*)(x + (size_t)(r0 + row) * 512 + c4 * 4);
        __nv_bfloat162* d = (__nv_bfloat162*)&xs[(size_t)row * LDA_X + c4 * 4];
        d[0] = __floats2bfloat162_rn(v.x, v.y);
        d[1] = __floats2bfloat162_rn(v.z, v.w);
    }
    for (int i = tid; i < 384; i += 256)                  // FIXED: full coverage
        rout[i] = g_routing[(size_t)r0 * 6 + i];
    if (tid < 128) { oacc[tid] = 0.f; oacc[tid + 128] = 0.f; }
    __syncthreads();

    for (int e = 0; e < 6; ++e) {
        const __nv_bfloat16* W1 = g_We1b + (size_t)e * 512 * 1024;
        const float* b1 = be1 + e * 1024;
        for (int nc = 0; nc < 1024; nc += 128)
            mma_chunk<0>(xs, LDA_X, 512, W1 + nc, 1024, ws, ws_u32, b1 + nc,
                         h1s, nc, nullptr, nullptr);
        __syncthreads();   // h1 complete before any warp reads it

        float s[4][3];
#pragma unroll
        for (int rt = 0; rt < 4; ++rt)
#pragma unroll
            for (int o = 0; o < 3; ++o) s[rt][o] = 0.f;

        const __nv_bfloat16* W2 = g_We2b + (size_t)e * 1024 * 512;
        const float* b2 = be2 + e * 512;
        const float* w3 = We3 + (size_t)e * 1536;
        for (int nc = 0; nc < 512; nc += 128)
            mma_chunk<1>(h1s, LDA_H1, 1024, W2 + nc, 512, ws, ws_u32, b2 + nc,
                         nullptr, nc, w3, s);

#pragma unroll
        for (int rt = 0; rt < 4; ++rt)
#pragma unroll
            for (int o = 0; o < 3; ++o) {
                s[rt][o] += __shfl_xor_sync(0xffffffffu, s[rt][o], 1);
                s[rt][o] += __shfl_xor_sync(0xffffffffu, s[rt][o], 2);
            }
        if ((lane & 3) == 0) {
            float bz[3];
#pragma unroll
            for (int o = 0; o < 3; ++o)
                bz[o] = (wc == 0) ? be3[e * 3 + o] : 0.f;
#pragma unroll
            for (int rt = 0; rt < 4; ++rt) {
                int row = wr * 32 + (rt >> 1) * 16 + (lane >> 2) + 8 * (rt & 1);
                float rw = rout[row * 6 + e];
#pragma unroll
                for (int o = 0; o < 3; ++o)
                    atomicAdd(&oacc[row * 4 + o], rw * (s[rt][o] + bz[o]));
            }
        }
        __syncthreads();   // oacc settle + h1 readers done before next expert
    }

    if (tid < 8) {
        float f0 = 0.f, f1 = 0.f, f2 = 0.f;
#pragma unroll
        for (int i = 0; i < 8; ++i) {
            f0 += oacc[(tid * 8 + i) * 4 + 0];
            f1 += oacc[(tid * 8 + i) * 4 + 1];
            f2 += oacc[(tid * 8 + i) * 4 + 2];
        }
        f0 *= 0.125f; f1 *= 0.125f; f2 *= 0.125f;
        float a1[16];
#pragma unroll
        for (int j = 0; j < 16; ++j) {
            float v = ba1[j] + f0 * Wa1[j] + f1 * Wa1[16 + j] + f2 * Wa1[32 + j];
            a1[j] = fmaxf(v, 0.f);
        }
        int b = blockIdx.x * 8 + tid;
#pragma unroll
        for (int o = 0; o < 3; ++o) {
            float v = ba2[o];
#pragma unroll
            for (int j = 0; j < 16; ++j) v = fmaf(a1[j], Wa2[j * 3 + o], v);
            out[b * 3 + o] = v;
        }
    }
}

// ---------------- launch ----------------
extern "C" void kernel_launch(void* const* d_in, const int* in_sizes, int n_in,
                              void* d_out, int out_size) {
    const float* x   = (const float*)d_in[0];
    const float* Wr1 = (const float*)d_in[1];
    const float* br1 = (const float*)d_in[2];
    const float* Wr2 = (const float*)d_in[3];
    const float* br2 = (const float*)d_in[4];
    const float* We1 = (const float*)d_in[5];
    const float* be1 = (const float*)d_in[6];
    const float* We2 = (const float*)d_in[7];
    const float* be2 = (const float*)d_in[8];
    const float* We3 = (const float*)d_in[9];
    const float* be3 = (const float*)d_in[10];
    const float* Wa1 = (const float*)d_in[11];
    const float* ba1 = (const float*)d_in[12];
    const float* Wa2 = (const float*)d_in[13];
    const float* ba2 = (const float*)d_in[14];
    float* out = (float*)d_out;

    const int SMEM_R = (64 * 512 + 512 * 32 + 64 * 32 + 192 + 32 + 8) * 4;
    const int SMEM_M = 227328;

    cudaFuncSetAttribute(routing_kernel, cudaFuncAttributeMaxDynamicSharedMemorySize, SMEM_R);
    cudaFuncSetAttribute(moe_kernel, cudaFuncAttributeMaxDynamicSharedMemorySize, SMEM_M);

    prep_kernel<<<3072, 256>>>(We1, We2);
    routing_kernel<<<dim3(64, 8), 256, SMEM_R>>>(x, Wr1, br1, Wr2, br2);
    moe_kernel<<<512, 256, SMEM_M>>>(x, be1, be2, We3, be3,
                                     Wa1, ba1, Wa2, ba2, out);
}

// round 14
// speedup vs baseline: 1.5971x; 1.4017x over previous
#include <cuda_runtime.h>
#include <cuda_bf16.h>
#include <cstdint>

// bf16 mma.sync fused MoE-PINN — R6 schedule, pair-grouped commits (6-slot ring),
// wait at top of iteration (4-stage prefetch distance), rout fix.

__device__ __nv_bfloat16 g_We1b[6 * 512 * 1024];
__device__ __nv_bfloat16 g_We2b[6 * 1024 * 512];
__device__ float g_routing[32768 * 6];

__device__ __forceinline__ float fast_tanh(float x) {
    float e = __expf(2.0f * x);
    return 1.0f - __fdividef(2.0f, e + 1.0f);
}
__device__ __forceinline__ uint32_t smem_u32(const void* p) {
    return (uint32_t)__cvta_generic_to_shared(p);
}
__device__ __forceinline__ void ldsm_x4(uint32_t (&r)[4], uint32_t a) {
    asm volatile("ldmatrix.sync.aligned.m8n8.x4.shared.b16 {%0,%1,%2,%3}, [%4];"
        : "=r"(r[0]), "=r"(r[1]), "=r"(r[2]), "=r"(r[3]) : "r"(a));
}
__device__ __forceinline__ void ldsm_x4_t(uint32_t (&r)[4], uint32_t a) {
    asm volatile("ldmatrix.sync.aligned.m8n8.x4.trans.shared.b16 {%0,%1,%2,%3}, [%4];"
        : "=r"(r[0]), "=r"(r[1]), "=r"(r[2]), "=r"(r[3]) : "r"(a));
}
__device__ __forceinline__ void mma_bf16(float (&d)[4], const uint32_t (&a)[4],
                                         uint32_t b0, uint32_t b1) {
    asm volatile(
        "mma.sync.aligned.m16n8k16.row.col.f32.bf16.bf16.f32 "
        "{%0,%1,%2,%3}, {%4,%5,%6,%7}, {%8,%9}, {%0,%1,%2,%3};"
        : "+f"(d[0]), "+f"(d[1]), "+f"(d[2]), "+f"(d[3])
        : "r"(a[0]), "r"(a[1]), "r"(a[2]), "r"(a[3]), "r"(b0), "r"(b1));
}
__device__ __forceinline__ void cp16(uint32_t dst, const void* src) {
    asm volatile("cp.async.cg.shared.global [%0], [%1], 16;" :: "r"(dst), "l"(src));
}
__device__ __forceinline__ void cp_commit() { asm volatile("cp.async.commit_group;"); }
__device__ __forceinline__ void cp_wait0() { asm volatile("cp.async.wait_group 0;"); }
__device__ __forceinline__ void cp_wait1() { asm volatile("cp.async.wait_group 1;"); }

// ---------------- prep: convert We1/We2 to bf16 ----------------
__global__ __launch_bounds__(256) void prep_kernel(
    const float* __restrict__ We1, const float* __restrict__ We2)
{
    const size_t N4 = (size_t)6 * 512 * 1024 / 4;
    size_t i = (size_t)blockIdx.x * 256 + threadIdx.x;
    if (i < N4) {
        float4 v = ((const float4*)We1)[i];
        ((__nv_bfloat162*)g_We1b)[i * 2]     = __floats2bfloat162_rn(v.x, v.y);
        ((__nv_bfloat162*)g_We1b)[i * 2 + 1] = __floats2bfloat162_rn(v.z, v.w);
        float4 w = ((const float4*)We2)[i];
        ((__nv_bfloat162*)g_We2b)[i * 2]     = __floats2bfloat162_rn(w.x, w.y);
        ((__nv_bfloat162*)g_We2b)[i * 2 + 1] = __floats2bfloat162_rn(w.z, w.w);
    }
}

// ---------------- routing kernel (fp32, proven) ----------------
__global__ __launch_bounds__(256, 1) void routing_kernel(
    const float* __restrict__ x,
    const float* __restrict__ Wr1, const float* __restrict__ br1,
    const float* __restrict__ Wr2, const float* __restrict__ br2)
{
    extern __shared__ char smraw[];
    float* xs = (float*)smraw;
    float* w1 = xs + 64 * 512;
    float* r1 = w1 + 512 * 32;
    float* w2 = r1 + 64 * 32;
    float* b1 = w2 + 192;
    float* b2 = b1 + 32;
    const int s = blockIdx.y, b0 = blockIdx.x * 64, tid = threadIdx.x;

    for (int i = tid; i < 64 * 512 / 4; i += 256) {
        int row = i >> 7, c4 = i & 127;
        ((float4*)xs)[i] = *(const float4*)(x + (size_t)(b0 + row) * 4096 + s * 512 + c4 * 4);
    }
    const float* w1g = Wr1 + (size_t)s * 512 * 32;
    for (int i = tid; i < 512 * 32 / 4; i += 256)
        ((float4*)w1)[i] = ((const float4*)w1g)[i];
    if (tid < 32)  b1[tid] = br1[s * 32 + tid];
    if (tid < 192) w2[tid] = Wr2[s * 192 + tid];
    if (tid < 6)   b2[tid] = br2[s * 6 + tid];
    __syncthreads();
    {
        int h = tid & 31, rg = tid >> 5;
        float acc[8];
#pragma unroll
        for (int r = 0; r < 8; ++r) acc[r] = 0.f;
        for (int k = 0; k < 512; ++k) {
            float w = w1[k * 32 + h];
#pragma unroll
            for (int r = 0; r < 8; ++r)
                acc[r] = fmaf(xs[(rg * 8 + r) * 512 + k], w, acc[r]);
        }
#pragma unroll
        for (int r = 0; r < 8; ++r)
            r1[(rg * 8 + r) * 32 + h] = fmaxf(acc[r] + b1[h], 0.f);
    }
    __syncthreads();
    if (tid < 64) {
        float lg[6];
#pragma unroll
        for (int e = 0; e < 6; ++e) lg[e] = b2[e];
        for (int h = 0; h < 32; ++h) {
            float rv = r1[tid * 32 + h];
#pragma unroll
            for (int e = 0; e < 6; ++e) lg[e] = fmaf(rv, w2[h * 6 + e], lg[e]);
        }
        float mx = lg[0];
#pragma unroll
        for (int e = 1; e < 6; ++e) mx = fmaxf(mx, lg[e]);
        float sum = 0.f;
#pragma unroll
        for (int e = 0; e < 6; ++e) { lg[e] = __expf(lg[e] - mx); sum += lg[e]; }
        float inv = 1.f / sum;
        int r = (b0 + tid) * 8 + s;
#pragma unroll
        for (int e = 0; e < 6; ++e) g_routing[r * 6 + e] = lg[e] * inv;
    }
}

// -------- GEMM chunk: pair-grouped commits, wait-at-top, 6-slot ring --------
#define LDA_X 520
#define LDA_H1 1032
#define WS_STRIDE 136
#define WS_BUF_E (16 * WS_STRIDE)   // elems / stage slot
#define WS_BUF_B (WS_BUF_E * 2)     // bytes / stage slot

template <int MODE>
__device__ __forceinline__ void mma_chunk(
    const __nv_bfloat16* __restrict__ Asm, int lda, int K,
    const __nv_bfloat16* __restrict__ Wg, int ldw,
    const __nv_bfloat16* __restrict__ ws, uint32_t ws_u32,
    const float* __restrict__ biasg,
    __nv_bfloat16* __restrict__ h1out, int nc,
    const float* __restrict__ we3g, float (*s)[3])
{
    const int tid = threadIdx.x;
    const int lane = tid & 31, warp = tid >> 5;
    const int wr = warp >> 2, wc = warp & 3;
    const int rowbase = wr * 32, colbase = wc * 32;
    const int li = lane & 15, lj = lane >> 4;

    float c[2][4][4];
#pragma unroll
    for (int mt = 0; mt < 2; ++mt)
#pragma unroll
        for (int nt = 0; nt < 4; ++nt)
#pragma unroll
            for (int v = 0; v < 4; ++v) c[mt][nt][v] = 0.f;

    const int crow = tid >> 4;            // 0..15
    const int ccol = (tid & 15) * 8;
    const uint32_t dst0 = ws_u32 + (uint32_t)(crow * WS_STRIDE + ccol) * 2;
    const __nv_bfloat16* src0 = Wg + (size_t)crow * ldw + ccol;
    const int nst = K >> 4;               // 32 or 64 (even)
    const int niter = nst >> 1;

    // prologue: guard ws vs previous chunk readers, commit G0={0,1}, G1={2,3}
    __syncthreads();
    cp16(dst0 + 0u * WS_BUF_B, src0);
    cp16(dst0 + 1u * WS_BUF_B, src0 + (size_t)16 * ldw);
    cp_commit();
    cp16(dst0 + 2u * WS_BUF_B, src0 + (size_t)32 * ldw);
    cp16(dst0 + 3u * WS_BUF_B, src0 + (size_t)48 * ldw);
    cp_commit();

    const __nv_bfloat16* a0p = Asm + (size_t)(rowbase + li) * lda + lj * 8;
    const __nv_bfloat16* a1p = a0p + (size_t)16 * lda;
    const __nv_bfloat16* bp  = ws + li * WS_STRIDE + colbase + lj * 8;

    int sc = 0;   // compute slot base = (2*it) % 6
    int sf = 4;   // fill slot base    = (2*it + 4) % 6
    for (int it = 0; it < niter; ++it) {
        // G_it landed (committed 2 iterations / 4 stages earlier)
        if (it + 1 < niter) cp_wait1(); else cp_wait0();
        __syncthreads();   // publish G_it; retire iter it-1 readers of slots sf

        if (2 * it + 4 < nst) {
            const __nv_bfloat16* sg = src0 + (size_t)(2 * it + 4) * 16 * ldw;
            cp16(dst0 + (uint32_t)sf * WS_BUF_B, sg);
            cp16(dst0 + (uint32_t)(sf + 1) * WS_BUF_B, sg + (size_t)16 * ldw);
            cp_commit();
        }

        // compute stage 2*it (slot sc)
        {
            uint32_t a[2][4], b[2][4];
            ldsm_x4(a[0], smem_u32(a0p + (2 * it) * 16));
            ldsm_x4(a[1], smem_u32(a1p + (2 * it) * 16));
            const __nv_bfloat16* wb = bp + sc * WS_BUF_E;
            ldsm_x4_t(b[0], smem_u32(wb));
            ldsm_x4_t(b[1], smem_u32(wb + 16));
#pragma unroll
            for (int mt = 0; mt < 2; ++mt)
#pragma unroll
                for (int nt = 0; nt < 4; ++nt)
                    mma_bf16(c[mt][nt], a[mt], b[nt >> 1][(nt & 1) * 2],
                             b[nt >> 1][(nt & 1) * 2 + 1]);
        }
        // compute stage 2*it+1 (slot sc+1)
        {
            uint32_t a[2][4], b[2][4];
            ldsm_x4(a[0], smem_u32(a0p + (2 * it + 1) * 16));
            ldsm_x4(a[1], smem_u32(a1p + (2 * it + 1) * 16));
            const __nv_bfloat16* wb = bp + (sc + 1) * WS_BUF_E;
            ldsm_x4_t(b[0], smem_u32(wb));
            ldsm_x4_t(b[1], smem_u32(wb + 16));
#pragma unroll
            for (int mt = 0; mt < 2; ++mt)
#pragma unroll
                for (int nt = 0; nt < 4; ++nt)
                    mma_bf16(c[mt][nt], a[mt], b[nt >> 1][(nt & 1) * 2],
                             b[nt >> 1][(nt & 1) * 2 + 1]);
        }

        sc += 2; if (sc == 6) sc = 0;
        sf += 2; if (sf == 6) sf = 0;
    }

    // epilogue
#pragma unroll
    for (int mt = 0; mt < 2; ++mt) {
#pragma unroll
        for (int nt = 0; nt < 4; ++nt) {
            const int colc = colbase + nt * 8 + 2 * (lane & 3);
            float2 bb = *(const float2*)(biasg + colc);
            float t0 = fast_tanh(c[mt][nt][0] + bb.x);
            float t1 = fast_tanh(c[mt][nt][1] + bb.y);
            float t2 = fast_tanh(c[mt][nt][2] + bb.x);
            float t3 = fast_tanh(c[mt][nt][3] + bb.y);
            const int ra = rowbase + mt * 16 + (lane >> 2);
            if (MODE == 0) {
                __nv_bfloat162 p0 = __floats2bfloat162_rn(t0, t1);
                __nv_bfloat162 p1 = __floats2bfloat162_rn(t2, t3);
                *(__nv_bfloat162*)&h1out[(size_t)ra * LDA_H1 + nc + colc] = p0;
                *(__nv_bfloat162*)&h1out[(size_t)(ra + 8) * LDA_H1 + nc + colc] = p1;
            } else {
                const float* w3a = we3g + (size_t)(nc + colc) * 3;
#pragma unroll
                for (int o = 0; o < 3; ++o) {
                    float wa = w3a[o], wb2 = w3a[3 + o];
                    s[mt * 2 + 0][o] += t0 * wa + t1 * wb2;
                    s[mt * 2 + 1][o] += t2 * wa + t3 * wb2;
                }
            }
        }
    }
}

// ---------------- main fused kernel: 512 CTAs x 256 threads ----------------
// smem: xs 66560 | h1 132096 | ws 26112 | rout 1536 | oacc 1024 => 227328
__global__ __launch_bounds__(256, 1) void moe_kernel(
    const float* __restrict__ x,
    const float* __restrict__ be1, const float* __restrict__ be2,
    const float* __restrict__ We3, const float* __restrict__ be3,
    const float* __restrict__ Wa1, const float* __restrict__ ba1,
    const float* __restrict__ Wa2, const float* __restrict__ ba2,
    float* __restrict__ out)
{
    extern __shared__ char smraw[];
    __nv_bfloat16* xs   = (__nv_bfloat16*)(smraw);
    __nv_bfloat16* h1s  = (__nv_bfloat16*)(smraw + 66560);
    __nv_bfloat16* ws   = (__nv_bfloat16*)(smraw + 198656);
    float*         rout = (float*)(smraw + 224768);
    float*         oacc = (float*)(smraw + 226304);

    const int tid = threadIdx.x;
    const int lane = tid & 31, warp = tid >> 5;
    const int wr = warp >> 2, wc = warp & 3;
    const int r0 = blockIdx.x * 64;
    const uint32_t ws_u32 = smem_u32(ws);

    for (int i = tid; i < 64 * 512 / 4; i += 256) {
        int row = i >> 7, c4 = i & 127;
        float4 v = *(const float4*)(x + (size_t)(r0 + row) * 512 + c4 * 4);
        __nv_bfloat162* d = (__nv_bfloat162*)&xs[(size_t)row * LDA_X + c4 * 4];
        d[0] = __floats2bfloat162_rn(v.x, v.y);
        d[1] = __floats2bfloat162_rn(v.z, v.w);
    }
    for (int i = tid; i < 384; i += 256)   // full coverage (384 entries)
        rout[i] = g_routing[(size_t)r0 * 6 + i];
    if (tid < 128) { oacc[tid] = 0.f; oacc[tid + 128] = 0.f; }
    __syncthreads();

    for (int e = 0; e < 6; ++e) {
        const __nv_bfloat16* W1 = g_We1b + (size_t)e * 512 * 1024;
        const float* b1 = be1 + e * 1024;
        for (int nc = 0; nc < 1024; nc += 128)
            mma_chunk<0>(xs, LDA_X, 512, W1 + nc, 1024, ws, ws_u32, b1 + nc,
                         h1s, nc, nullptr, nullptr);
        __syncthreads();   // h1 complete before any warp reads it

        float s[4][3];
#pragma unroll
        for (int rt = 0; rt < 4; ++rt)
#pragma unroll
            for (int o = 0; o < 3; ++o) s[rt][o] = 0.f;

        const __nv_bfloat16* W2 = g_We2b + (size_t)e * 1024 * 512;
        const float* b2 = be2 + e * 512;
        const float* w3 = We3 + (size_t)e * 1536;
        for (int nc = 0; nc < 512; nc += 128)
            mma_chunk<1>(h1s, LDA_H1, 1024, W2 + nc, 512, ws, ws_u32, b2 + nc,
                         nullptr, nc, w3, s);

#pragma unroll
        for (int rt = 0; rt < 4; ++rt)
#pragma unroll
            for (int o = 0; o < 3; ++o) {
                s[rt][o] += __shfl_xor_sync(0xffffffffu, s[rt][o], 1);
                s[rt][o] += __shfl_xor_sync(0xffffffffu, s[rt][o], 2);
            }
        if ((lane & 3) == 0) {
            float bz[3];
#pragma unroll
            for (int o = 0; o < 3; ++o)
                bz[o] = (wc == 0) ? be3[e * 3 + o] : 0.f;
#pragma unroll
            for (int rt = 0; rt < 4; ++rt) {
                int row = wr * 32 + (rt >> 1) * 16 + (lane >> 2) + 8 * (rt & 1);
                float rw = rout[row * 6 + e];
#pragma unroll
                for (int o = 0; o < 3; ++o)
                    atomicAdd(&oacc[row * 4 + o], rw * (s[rt][o] + bz[o]));
            }
        }
        __syncthreads();   // oacc settle + h1 readers done before next expert
    }

    if (tid < 8) {
        float f0 = 0.f, f1 = 0.f, f2 = 0.f;
#pragma unroll
        for (int i = 0; i < 8; ++i) {
            f0 += oacc[(tid * 8 + i) * 4 + 0];
            f1 += oacc[(tid * 8 + i) * 4 + 1];
            f2 += oacc[(tid * 8 + i) * 4 + 2];
        }
        f0 *= 0.125f; f1 *= 0.125f; f2 *= 0.125f;
        float a1[16];
#pragma unroll
        for (int j = 0; j < 16; ++j) {
            float v = ba1[j] + f0 * Wa1[j] + f1 * Wa1[16 + j] + f2 * Wa1[32 + j];
            a1[j] = fmaxf(v, 0.f);
        }
        int b = blockIdx.x * 8 + tid;
#pragma unroll
        for (int o = 0; o < 3; ++o) {
            float v = ba2[o];
#pragma unroll
            for (int j = 0; j < 16; ++j) v = fmaf(a1[j], Wa2[j * 3 + o], v);
            out[b * 3 + o] = v;
        }
    }
}

// ---------------- launch ----------------
extern "C" void kernel_launch(void* const* d_in, const int* in_sizes, int n_in,
                              void* d_out, int out_size) {
    const float* x   = (const float*)d_in[0];
    const float* Wr1 = (const float*)d_in[1];
    const float* br1 = (const float*)d_in[2];
    const float* Wr2 = (const float*)d_in[3];
    const float* br2 = (const float*)d_in[4];
    const float* We1 = (const float*)d_in[5];
    const float* be1 = (const float*)d_in[6];
    const float* We2 = (const float*)d_in[7];
    const float* be2 = (const float*)d_in[8];
    const float* We3 = (const float*)d_in[9];
    const float* be3 = (const float*)d_in[10];
    const float* Wa1 = (const float*)d_in[11];
    const float* ba1 = (const float*)d_in[12];
    const float* Wa2 = (const float*)d_in[13];
    const float* ba2 = (const float*)d_in[14];
    float* out = (float*)d_out;

    const int SMEM_R = (64 * 512 + 512 * 32 + 64 * 32 + 192 + 32 + 8) * 4;
    const int SMEM_M = 227328;

    cudaFuncSetAttribute(routing_kernel, cudaFuncAttributeMaxDynamicSharedMemorySize, SMEM_R);
    cudaFuncSetAttribute(moe_kernel, cudaFuncAttributeMaxDynamicSharedMemorySize, SMEM_M);

    prep_kernel<<<3072, 256>>>(We1, We2);
    routing_kernel<<<dim3(64, 8), 256, SMEM_R>>>(x, Wr1, br1, Wr2, br2);
    moe_kernel<<<512, 256, SMEM_M>>>(x, be1, be2, We3, be3,
                                     Wa1, ba1, Wa2, ba2, out);
}

// round 15
// speedup vs baseline: 1.7720x; 1.1095x over previous
#include <cuda_runtime.h>
#include <cuda_bf16.h>
#include <cstdint>

// bf16 mma.sync fused MoE-PINN — (tile,expert) grid (3072 CTAs, ~1% tail),
// pair-grouped commits, 6-slot ring, global weighted-accumulate + agg kernel.

__device__ __nv_bfloat16 g_We1b[6 * 512 * 1024];
__device__ __nv_bfloat16 g_We2b[6 * 1024 * 512];
__device__ float g_routing[32768 * 6];
__device__ float g_wacc[32768 * 3];

__device__ __forceinline__ float fast_tanh(float x) {
    float e = __expf(2.0f * x);
    return 1.0f - __fdividef(2.0f, e + 1.0f);
}
__device__ __forceinline__ uint32_t smem_u32(const void* p) {
    return (uint32_t)__cvta_generic_to_shared(p);
}
__device__ __forceinline__ void ldsm_x4(uint32_t (&r)[4], uint32_t a) {
    asm volatile("ldmatrix.sync.aligned.m8n8.x4.shared.b16 {%0,%1,%2,%3}, [%4];"
        : "=r"(r[0]), "=r"(r[1]), "=r"(r[2]), "=r"(r[3]) : "r"(a));
}
__device__ __forceinline__ void ldsm_x4_t(uint32_t (&r)[4], uint32_t a) {
    asm volatile("ldmatrix.sync.aligned.m8n8.x4.trans.shared.b16 {%0,%1,%2,%3}, [%4];"
        : "=r"(r[0]), "=r"(r[1]), "=r"(r[2]), "=r"(r[3]) : "r"(a));
}
__device__ __forceinline__ void mma_bf16(float (&d)[4], const uint32_t (&a)[4],
                                         uint32_t b0, uint32_t b1) {
    asm volatile(
        "mma.sync.aligned.m16n8k16.row.col.f32.bf16.bf16.f32 "
        "{%0,%1,%2,%3}, {%4,%5,%6,%7}, {%8,%9}, {%0,%1,%2,%3};"
        : "+f"(d[0]), "+f"(d[1]), "+f"(d[2]), "+f"(d[3])
        : "r"(a[0]), "r"(a[1]), "r"(a[2]), "r"(a[3]), "r"(b0), "r"(b1));
}
__device__ __forceinline__ void cp16(uint32_t dst, const void* src) {
    asm volatile("cp.async.cg.shared.global [%0], [%1], 16;" :: "r"(dst), "l"(src));
}
__device__ __forceinline__ void cp_commit() { asm volatile("cp.async.commit_group;"); }
__device__ __forceinline__ void cp_wait0() { asm volatile("cp.async.wait_group 0;"); }
__device__ __forceinline__ void cp_wait1() { asm volatile("cp.async.wait_group 1;"); }

// ---------------- prep: convert We1/We2 to bf16 ----------------
__global__ __launch_bounds__(256) void prep_kernel(
    const float* __restrict__ We1, const float* __restrict__ We2)
{
    const size_t N4 = (size_t)6 * 512 * 1024 / 4;
    size_t i = (size_t)blockIdx.x * 256 + threadIdx.x;
    if (i < N4) {
        float4 v = ((const float4*)We1)[i];
        ((__nv_bfloat162*)g_We1b)[i * 2]     = __floats2bfloat162_rn(v.x, v.y);
        ((__nv_bfloat162*)g_We1b)[i * 2 + 1] = __floats2bfloat162_rn(v.z, v.w);
        float4 w = ((const float4*)We2)[i];
        ((__nv_bfloat162*)g_We2b)[i * 2]     = __floats2bfloat162_rn(w.x, w.y);
        ((__nv_bfloat162*)g_We2b)[i * 2 + 1] = __floats2bfloat162_rn(w.z, w.w);
    }
}

// ---------------- routing kernel (also zeros g_wacc) ----------------
__global__ __launch_bounds__(256, 1) void routing_kernel(
    const float* __restrict__ x,
    const float* __restrict__ Wr1, const float* __restrict__ br1,
    const float* __restrict__ Wr2, const float* __restrict__ br2)
{
    extern __shared__ char smraw[];
    float* xs = (float*)smraw;
    float* w1 = xs + 64 * 512;
    float* r1 = w1 + 512 * 32;
    float* w2 = r1 + 64 * 32;
    float* b1 = w2 + 192;
    float* b2 = b1 + 32;
    const int s = blockIdx.y, b0 = blockIdx.x * 64, tid = threadIdx.x;

    // zero the weighted-accumulator scratch (512 blocks x 256 thr = 131072 >= 98304)
    {
        int gidx = (blockIdx.y * 64 + blockIdx.x) * 256 + tid;
        if (gidx < 32768 * 3) g_wacc[gidx] = 0.f;
    }

    for (int i = tid; i < 64 * 512 / 4; i += 256) {
        int row = i >> 7, c4 = i & 127;
        ((float4*)xs)[i] = *(const float4*)(x + (size_t)(b0 + row) * 4096 + s * 512 + c4 * 4);
    }
    const float* w1g = Wr1 + (size_t)s * 512 * 32;
    for (int i = tid; i < 512 * 32 / 4; i += 256)
        ((float4*)w1)[i] = ((const float4*)w1g)[i];
    if (tid < 32)  b1[tid] = br1[s * 32 + tid];
    if (tid < 192) w2[tid] = Wr2[s * 192 + tid];
    if (tid < 6)   b2[tid] = br2[s * 6 + tid];
    __syncthreads();
    {
        int h = tid & 31, rg = tid >> 5;
        float acc[8];
#pragma unroll
        for (int r = 0; r < 8; ++r) acc[r] = 0.f;
        for (int k = 0; k < 512; ++k) {
            float w = w1[k * 32 + h];
#pragma unroll
            for (int r = 0; r < 8; ++r)
                acc[r] = fmaf(xs[(rg * 8 + r) * 512 + k], w, acc[r]);
        }
#pragma unroll
        for (int r = 0; r < 8; ++r)
            r1[(rg * 8 + r) * 32 + h] = fmaxf(acc[r] + b1[h], 0.f);
    }
    __syncthreads();
    if (tid < 64) {
        float lg[6];
#pragma unroll
        for (int e = 0; e < 6; ++e) lg[e] = b2[e];
        for (int h = 0; h < 32; ++h) {
            float rv = r1[tid * 32 + h];
#pragma unroll
            for (int e = 0; e < 6; ++e) lg[e] = fmaf(rv, w2[h * 6 + e], lg[e]);
        }
        float mx = lg[0];
#pragma unroll
        for (int e = 1; e < 6; ++e) mx = fmaxf(mx, lg[e]);
        float sum = 0.f;
#pragma unroll
        for (int e = 0; e < 6; ++e) { lg[e] = __expf(lg[e] - mx); sum += lg[e]; }
        float inv = 1.f / sum;
        int r = (b0 + tid) * 8 + s;
#pragma unroll
        for (int e = 0; e < 6; ++e) g_routing[r * 6 + e] = lg[e] * inv;
    }
}

// -------- GEMM chunk: pair-grouped commits, wait-at-top, 6-slot ring --------
#define LDA_X 520
#define LDA_H1 1032
#define WS_STRIDE 136
#define WS_BUF_E (16 * WS_STRIDE)
#define WS_BUF_B (WS_BUF_E * 2)

template <int MODE>
__device__ __forceinline__ void mma_chunk(
    const __nv_bfloat16* __restrict__ Asm, int lda, int K,
    const __nv_bfloat16* __restrict__ Wg, int ldw,
    const __nv_bfloat16* __restrict__ ws, uint32_t ws_u32,
    const float* __restrict__ biasg,
    __nv_bfloat16* __restrict__ h1out, int nc,
    const float* __restrict__ we3g, float (*s)[3])
{
    const int tid = threadIdx.x;
    const int lane = tid & 31, warp = tid >> 5;
    const int wr = warp >> 2, wc = warp & 3;
    const int rowbase = wr * 32, colbase = wc * 32;
    const int li = lane & 15, lj = lane >> 4;

    float c[2][4][4];
#pragma unroll
    for (int mt = 0; mt < 2; ++mt)
#pragma unroll
        for (int nt = 0; nt < 4; ++nt)
#pragma unroll
            for (int v = 0; v < 4; ++v) c[mt][nt][v] = 0.f;

    const int crow = tid >> 4;
    const int ccol = (tid & 15) * 8;
    const uint32_t dst0 = ws_u32 + (uint32_t)(crow * WS_STRIDE + ccol) * 2;
    const __nv_bfloat16* src0 = Wg + (size_t)crow * ldw + ccol;
    const int nst = K >> 4;
    const int niter = nst >> 1;

    // prologue: guard ws vs previous chunk readers; commit G0={0,1}, G1={2,3}
    __syncthreads();
    cp16(dst0 + 0u * WS_BUF_B, src0);
    cp16(dst0 + 1u * WS_BUF_B, src0 + (size_t)16 * ldw);
    cp_commit();
    cp16(dst0 + 2u * WS_BUF_B, src0 + (size_t)32 * ldw);
    cp16(dst0 + 3u * WS_BUF_B, src0 + (size_t)48 * ldw);
    cp_commit();

    const __nv_bfloat16* a0p = Asm + (size_t)(rowbase + li) * lda + lj * 8;
    const __nv_bfloat16* a1p = a0p + (size_t)16 * lda;
    const __nv_bfloat16* bp  = ws + li * WS_STRIDE + colbase + lj * 8;

    int sc = 0, sf = 4;
    for (int it = 0; it < niter; ++it) {
        if (it + 1 < niter) cp_wait1(); else cp_wait0();
        __syncthreads();

        if (2 * it + 4 < nst) {
            const __nv_bfloat16* sg = src0 + (size_t)(2 * it + 4) * 16 * ldw;
            cp16(dst0 + (uint32_t)sf * WS_BUF_B, sg);
            cp16(dst0 + (uint32_t)(sf + 1) * WS_BUF_B, sg + (size_t)16 * ldw);
            cp_commit();
        }

        {
            uint32_t a[2][4], b[2][4];
            ldsm_x4(a[0], smem_u32(a0p + (2 * it) * 16));
            ldsm_x4(a[1], smem_u32(a1p + (2 * it) * 16));
            const __nv_bfloat16* wb = bp + sc * WS_BUF_E;
            ldsm_x4_t(b[0], smem_u32(wb));
            ldsm_x4_t(b[1], smem_u32(wb + 16));
#pragma unroll
            for (int mt = 0; mt < 2; ++mt)
#pragma unroll
                for (int nt = 0; nt < 4; ++nt)
                    mma_bf16(c[mt][nt], a[mt], b[nt >> 1][(nt & 1) * 2],
                             b[nt >> 1][(nt & 1) * 2 + 1]);
        }
        {
            uint32_t a[2][4], b[2][4];
            ldsm_x4(a[0], smem_u32(a0p + (2 * it + 1) * 16));
            ldsm_x4(a[1], smem_u32(a1p + (2 * it + 1) * 16));
            const __nv_bfloat16* wb = bp + (sc + 1) * WS_BUF_E;
            ldsm_x4_t(b[0], smem_u32(wb));
            ldsm_x4_t(b[1], smem_u32(wb + 16));
#pragma unroll
            for (int mt = 0; mt < 2; ++mt)
#pragma unroll
                for (int nt = 0; nt < 4; ++nt)
                    mma_bf16(c[mt][nt], a[mt], b[nt >> 1][(nt & 1) * 2],
                             b[nt >> 1][(nt & 1) * 2 + 1]);
        }

        sc += 2; if (sc == 6) sc = 0;
        sf += 2; if (sf == 6) sf = 0;
    }

    // epilogue
#pragma unroll
    for (int mt = 0; mt < 2; ++mt) {
#pragma unroll
        for (int nt = 0; nt < 4; ++nt) {
            const int colc = colbase + nt * 8 + 2 * (lane & 3);
            float2 bb = *(const float2*)(biasg + colc);
            float t0 = fast_tanh(c[mt][nt][0] + bb.x);
            float t1 = fast_tanh(c[mt][nt][1] + bb.y);
            float t2 = fast_tanh(c[mt][nt][2] + bb.x);
            float t3 = fast_tanh(c[mt][nt][3] + bb.y);
            const int ra = rowbase + mt * 16 + (lane >> 2);
            if (MODE == 0) {
                __nv_bfloat162 p0 = __floats2bfloat162_rn(t0, t1);
                __nv_bfloat162 p1 = __floats2bfloat162_rn(t2, t3);
                *(__nv_bfloat162*)&h1out[(size_t)ra * LDA_H1 + nc + colc] = p0;
                *(__nv_bfloat162*)&h1out[(size_t)(ra + 8) * LDA_H1 + nc + colc] = p1;
            } else {
                const float* w3a = we3g + (size_t)(nc + colc) * 3;
#pragma unroll
                for (int o = 0; o < 3; ++o) {
                    float wa = w3a[o], wb2 = w3a[3 + o];
                    s[mt * 2 + 0][o] += t0 * wa + t1 * wb2;
                    s[mt * 2 + 1][o] += t2 * wa + t3 * wb2;
                }
            }
        }
    }
}

// -------- main kernel: grid (512 tiles, 6 experts) x 256 threads --------
// smem: xs 66560 | h1 132096 | ws 26112 => 224768
__global__ __launch_bounds__(256, 1) void moe_kernel(
    const float* __restrict__ x,
    const float* __restrict__ be1, const float* __restrict__ be2,
    const float* __restrict__ We3, const float* __restrict__ be3)
{
    extern __shared__ char smraw[];
    __nv_bfloat16* xs  = (__nv_bfloat16*)(smraw);
    __nv_bfloat16* h1s = (__nv_bfloat16*)(smraw + 66560);
    __nv_bfloat16* ws  = (__nv_bfloat16*)(smraw + 198656);

    const int tid = threadIdx.x;
    const int lane = tid & 31, warp = tid >> 5;
    const int wr = warp >> 2, wc = warp & 3;
    const int r0 = blockIdx.x * 64;
    const int e  = blockIdx.y;
    const uint32_t ws_u32 = smem_u32(ws);

    for (int i = tid; i < 64 * 512 / 4; i += 256) {
        int row = i >> 7, c4 = i & 127;
        float4 v = *(const float4*)(x + (size_t)(r0 + row) * 512 + c4 * 4);
        __nv_bfloat162* d = (__nv_bfloat162*)&xs[(size_t)row * LDA_X + c4 * 4];
        d[0] = __floats2bfloat162_rn(v.x, v.y);
        d[1] = __floats2bfloat162_rn(v.z, v.w);
    }
    // (xs ordered before first A-read by mma_chunk's prologue barriers)

    const __nv_bfloat16* W1 = g_We1b + (size_t)e * 512 * 1024;
    const float* b1 = be1 + e * 1024;
    for (int nc = 0; nc < 1024; nc += 128)
        mma_chunk<0>(xs, LDA_X, 512, W1 + nc, 1024, ws, ws_u32, b1 + nc,
                     h1s, nc, nullptr, nullptr);
    __syncthreads();   // h1 complete before any warp reads it

    float s[4][3];
#pragma unroll
    for (int rt = 0; rt < 4; ++rt)
#pragma unroll
        for (int o = 0; o < 3; ++o) s[rt][o] = 0.f;

    const __nv_bfloat16* W2 = g_We2b + (size_t)e * 1024 * 512;
    const float* b2 = be2 + e * 512;
    const float* w3 = We3 + (size_t)e * 1536;
    for (int nc = 0; nc < 512; nc += 128)
        mma_chunk<1>(h1s, LDA_H1, 1024, W2 + nc, 512, ws, ws_u32, b2 + nc,
                     nullptr, nc, w3, s);

#pragma unroll
    for (int rt = 0; rt < 4; ++rt)
#pragma unroll
        for (int o = 0; o < 3; ++o) {
            s[rt][o] += __shfl_xor_sync(0xffffffffu, s[rt][o], 1);
            s[rt][o] += __shfl_xor_sync(0xffffffffu, s[rt][o], 2);
        }
    if ((lane & 3) == 0) {
        float bz[3];
#pragma unroll
        for (int o = 0; o < 3; ++o)
            bz[o] = (wc == 0) ? be3[e * 3 + o] : 0.f;
#pragma unroll
        for (int rt = 0; rt < 4; ++rt) {
            int row = wr * 32 + (rt >> 1) * 16 + (lane >> 2) + 8 * (rt & 1);
            float rw = g_routing[(size_t)(r0 + row) * 6 + e];
#pragma unroll
            for (int o = 0; o < 3; ++o)
                atomicAdd(&g_wacc[(size_t)(r0 + row) * 3 + o], rw * (s[rt][o] + bz[o]));
        }
    }
}

// -------- aggregator kernel: 16 blocks x 256 thr = 4096 batch items --------
__global__ __launch_bounds__(256) void agg_kernel(
    const float* __restrict__ Wa1, const float* __restrict__ ba1,
    const float* __restrict__ Wa2, const float* __restrict__ ba2,
    float* __restrict__ out)
{
    int b = blockIdx.x * 256 + threadIdx.x;   // 0..4095
    float f0 = 0.f, f1 = 0.f, f2 = 0.f;
#pragma unroll
    for (int i = 0; i < 8; ++i) {
        const float* w = &g_wacc[(size_t)(b * 8 + i) * 3];
        f0 += w[0]; f1 += w[1]; f2 += w[2];
    }
    f0 *= 0.125f; f1 *= 0.125f; f2 *= 0.125f;
    float a1[16];
#pragma unroll
    for (int j = 0; j < 16; ++j) {
        float v = ba1[j] + f0 * Wa1[j] + f1 * Wa1[16 + j] + f2 * Wa1[32 + j];
        a1[j] = fmaxf(v, 0.f);
    }
#pragma unroll
    for (int o = 0; o < 3; ++o) {
        float v = ba2[o];
#pragma unroll
        for (int j = 0; j < 16; ++j) v = fmaf(a1[j], Wa2[j * 3 + o], v);
        out[b * 3 + o] = v;
    }
}

// ---------------- launch ----------------
extern "C" void kernel_launch(void* const* d_in, const int* in_sizes, int n_in,
                              void* d_out, int out_size) {
    const float* x   = (const float*)d_in[0];
    const float* Wr1 = (const float*)d_in[1];
    const float* br1 = (const float*)d_in[2];
    const float* Wr2 = (const float*)d_in[3];
    const float* br2 = (const float*)d_in[4];
    const float* We1 = (const float*)d_in[5];
    const float* be1 = (const float*)d_in[6];
    const float* We2 = (const float*)d_in[7];
    const float* be2 = (const float*)d_in[8];
    const float* We3 = (const float*)d_in[9];
    const float* be3 = (const float*)d_in[10];
    const float* Wa1 = (const float*)d_in[11];
    const float* ba1 = (const float*)d_in[12];
    const float* Wa2 = (const float*)d_in[13];
    const float* ba2 = (const float*)d_in[14];
    float* out = (float*)d_out;

    const int SMEM_R = (64 * 512 + 512 * 32 + 64 * 32 + 192 + 32 + 8) * 4;
    const int SMEM_M = 224768;

    cudaFuncSetAttribute(routing_kernel, cudaFuncAttributeMaxDynamicSharedMemorySize, SMEM_R);
    cudaFuncSetAttribute(moe_kernel, cudaFuncAttributeMaxDynamicSharedMemorySize, SMEM_M);

    prep_kernel<<<3072, 256>>>(We1, We2);
    routing_kernel<<<dim3(64, 8), 256, SMEM_R>>>(x, Wr1, br1, Wr2, br2);
    moe_kernel<<<dim3(512, 6), 256, SMEM_M>>>(x, be1, be2, We3, be3);
    agg_kernel<<<16, 256>>>(Wa1, ba1, Wa2, ba2, out);
}